// round 17
// baseline (speedup 1.0000x reference)
#include <cuda_runtime.h>
#include <cuda_bf16.h>
#include <cstdint>

// out[b,n,d] = x[b,n] * W[n,d] + bias[n,d]   B=128, N=1024, D=512 fp32
//
// FINAL champion shape (R10): 4096 CTAs x 128 threads, 16 x STG.256/thread,
// W/b chunk register-resident, x staged via smem. Sweep evidence (wall us):
//   CTAs: 65536->58.1 | 8192->60.1 | 4096->44.1 | 2048->45.1 | 1024(256t)->47.7
//   -smem staging->45.5 | evict hints->45.8 | __stcs->regression
// Bound: 268MB compulsory fp32 output @ ~6.1 TB/s sustained + ~3.5us replay
// overhead. R16 polish: cap unroll at 8 -> tighter live range (48->~40 regs),
// occupancy back to ~62%; zero structural risk.

static constexpr int B_ = 128;
static constexpr int N_ = 1024;
static constexpr int D4 = 512 / 4;            // 128 float4 per row
static constexpr int ND4 = N_ * D4;           // 131072 float4 per batch row
static constexpr int B_PER_BLK = 16;

__device__ __forceinline__ uint64_t pack2(float lo, float hi) {
    uint64_t q;
    asm("mov.b64 %0, {%1, %2};" : "=l"(q) : "r"(__float_as_uint(lo)), "r"(__float_as_uint(hi)));
    return q;
}

__device__ __forceinline__ void st256(float4* p, float4 a, float4 b) {
    asm volatile("st.global.v4.b64 [%0], {%1,%2,%3,%4};"
                 :: "l"(p), "l"(pack2(a.x, a.y)), "l"(pack2(a.z, a.w)),
                    "l"(pack2(b.x, b.y)), "l"(pack2(b.z, b.w)) : "memory");
}

__global__ __launch_bounds__(128) void bcast_fma_st256_kernel(
    const float*  __restrict__ x,    // [B, N]
    const float4* __restrict__ W4,   // [N, D4]
    const float4* __restrict__ b4,   // [N, D4]
    float4*       __restrict__ out4) // [B, N, D4]
{
    const unsigned int tid     = threadIdx.x;       // 0..127
    const unsigned int n_local = tid >> 6;          // 0..1
    const unsigned int chunk   = tid & 63;          // 0..63 (32B chunks of a row)
    const unsigned int n       = blockIdx.x * 2 + n_local;
    const unsigned int b0      = blockIdx.y * B_PER_BLK;
    const unsigned int nd4     = n * D4 + chunk * 2;   // float4 index, 32B aligned

    // Weights/bias for this 32B chunk: loaded once, reused 16x in registers.
    const float4 w0 = W4[nd4],     w1 = W4[nd4 + 1];
    const float4 c0 = b4[nd4],     c1 = b4[nd4 + 1];

    // Stage x scalars: xs[n_local][i] = x[b0+i, n]
    __shared__ float xs[2][B_PER_BLK];
    if (tid < 2 * B_PER_BLK) {
        unsigned int nl = tid >> 4, i = tid & 15;
        xs[nl][i] = x[(b0 + i) * N_ + blockIdx.x * 2 + nl];
    }
    __syncthreads();

    unsigned int o_idx = b0 * ND4 + nd4;
    #pragma unroll 8
    for (int i = 0; i < B_PER_BLK; ++i) {
        const float s = xs[n_local][i];
        float4 o0, o1;
        o0.x = fmaf(s, w0.x, c0.x); o0.y = fmaf(s, w0.y, c0.y);
        o0.z = fmaf(s, w0.z, c0.z); o0.w = fmaf(s, w0.w, c0.w);
        o1.x = fmaf(s, w1.x, c1.x); o1.y = fmaf(s, w1.y, c1.y);
        o1.z = fmaf(s, w1.z, c1.z); o1.w = fmaf(s, w1.w, c1.w);
        st256(&out4[o_idx], o0, o1);
        o_idx += ND4;
    }
}

extern "C" void kernel_launch(void* const* d_in, const int* in_sizes, int n_in,
                              void* d_out, int out_size) {
    const float*  x  = (const float*)d_in[0];
    const float4* W4 = (const float4*)d_in[1];
    const float4* b4 = (const float4*)d_in[2];
    float4* out4 = (float4*)d_out;

    dim3 grid(N_ / 2, B_ / B_PER_BLK);   // 512 x 8 = 4096 blocks, 2 neurons/block
    bcast_fma_st256_kernel<<<grid, 128>>>(x, W4, b4, out4);
}